// round 12
// baseline (speedup 1.0000x reference)
#include <cuda_runtime.h>
#include <cuda_bf16.h>
#include <cstdint>

#define BB 16
#define MM 128
#define NH 256
#define EH 128
#define RR (BB*MM)          // 2048

typedef __nv_bfloat16 bf16;

// ---------------- scratch (all L2-resident) ----------------
__device__ __align__(128) float g_sA [RR];
__device__ __align__(128) float g_pO [3][RR * NH];
__device__ __align__(128) bf16 g_Xh [RR*NH],  g_Xl [RR*NH];
__device__ __align__(128) bf16 g_Xrh[RR*NH],  g_Xrl[RR*NH];
__device__ __align__(128) bf16 g_WvTh[NH*NH], g_WvTl[NH*NH];      // Wv^T [n][k]
__device__ __align__(128) bf16 g_WeTh[EH*EH], g_WeTl[EH*EH];      // We^T
__device__ __align__(128) bf16 g_WuTh[NH*640],g_WuTl[NH*640];     // Wu^T [n][k=640]
__device__ __align__(128) bf16 g_ATh[BB*MM*MM], g_ATl[BB*MM*MM];  // A^T [b][j][i]
__device__ __align__(128) bf16 g_NMTh[BB*NH*MM],g_NMTl[BB*NH*MM]; // nodeMap^T [b][n][i]
__device__ __align__(128) bf16 g_hNh[RR*NH],  g_hNl[RR*NH];
__device__ __align__(128) bf16 g_aEh[RR*EH],  g_aEl[RR*EH];
__device__ __align__(128) bf16 g_hEh[RR*EH],  g_hEl[RR*EH];

__device__ __forceinline__ void bsplit(float v, bf16& h, bf16& l) {
    h = __float2bfloat16(v);
    l = __float2bfloat16(v - __bfloat162float(h));
}

// ---------------- PTX helpers (all compute_103-legal) ----------------
__device__ __forceinline__ uint32_t smem_u32(const void* p) {
    uint32_t a;
    asm("{ .reg .u64 t; cvta.to.shared.u64 t, %1; cvt.u32.u64 %0, t; }" : "=r"(a) : "l"(p));
    return a;
}
__device__ __forceinline__ void cpa16(uint32_t dst, const void* src) {
    asm volatile("cp.async.cg.shared.global [%0], [%1], 16;" :: "r"(dst), "l"(src));
}
__device__ __forceinline__ void ldsm4(uint32_t* r, uint32_t a) {
    asm volatile("ldmatrix.sync.aligned.m8n8.x4.shared.b16 {%0,%1,%2,%3}, [%4];"
                 : "=r"(r[0]), "=r"(r[1]), "=r"(r[2]), "=r"(r[3]) : "r"(a));
}
__device__ __forceinline__ void ldsm2(uint32_t* r, uint32_t a) {
    asm volatile("ldmatrix.sync.aligned.m8n8.x2.shared.b16 {%0,%1}, [%2];"
                 : "=r"(r[0]), "=r"(r[1]) : "r"(a));
}
__device__ __forceinline__ void mma16816(float* c, const uint32_t* a, const uint32_t* b) {
    asm volatile(
        "mma.sync.aligned.m16n8k16.row.col.f32.bf16.bf16.f32 "
        "{%0,%1,%2,%3}, {%4,%5,%6,%7}, {%8,%9}, {%0,%1,%2,%3};"
        : "+f"(c[0]), "+f"(c[1]), "+f"(c[2]), "+f"(c[3])
        : "r"(a[0]), "r"(a[1]), "r"(a[2]), "r"(a[3]), "r"(b[0]), "r"(b[1]));
}

// ---------------------------------------------------------------------------
// Tensor-core GEMM: D[64,64] per CTA; D = A[M,K] . B[N,K]^T, split-bf16 x3.
//  EMODE 0: Pf[(rowBase+r)*ldp + col] = acc (fp32), + z*pStr
//  EMODE 1: v=acc+eb[n]; transposed split store Ph[b*NH*MM + n*MM + mlocal]
//  EMODE 2: v=relu(acc); row-major split store (ld=ldp, + z*pStr)
//  EMODE 3: v=relu(acc + sA[grow]*eb[n]); row-major split store
// ---------------------------------------------------------------------------
template <int KDIM, int EMODE>
__global__ __launch_bounds__(128) void tmm(
    const bf16* __restrict__ Ah, const bf16* __restrict__ Al, int lda, size_t aStr,
    const bf16* __restrict__ Bh, const bf16* __restrict__ Bl, int ldb, int kbOff, size_t bStr,
    const float* __restrict__ sAv, const float* __restrict__ eb,
    float* __restrict__ Pf, bf16* __restrict__ Ph, bf16* __restrict__ Pl,
    int ldp, size_t pStr)
{
    __shared__ bf16 sAh[2][64][40], sAl[2][64][40], sBh[2][64][40], sBl[2][64][40];

    int tid = threadIdx.x;
    int lane = tid & 31, wid = tid >> 5;
    int wm = (wid & 1) * 32, wn = (wid >> 1) * 32;
    int rowBase = blockIdx.x * 64, colBase = blockIdx.y * 64;
    int z = blockIdx.z;

    const bf16* gA0 = Ah + (size_t)z * aStr;
    const bf16* gA1 = Al + (size_t)z * aStr;
    const bf16* gB0 = Bh + (size_t)z * bStr;
    const bf16* gB1 = Bl + (size_t)z * bStr;

    int ldRow = tid >> 1;            // 0..63
    int ldSeg = (tid & 1) * 16;      // bf16 offset within 32-wide k-chunk

    auto loadStage = [&](int kt, int buf) {
        int k0 = kt * 32;
        const bf16* a0 = gA0 + (size_t)(rowBase + ldRow) * lda + k0 + ldSeg;
        const bf16* a1 = gA1 + (size_t)(rowBase + ldRow) * lda + k0 + ldSeg;
        const bf16* b0 = gB0 + (size_t)(colBase + ldRow) * ldb + kbOff + k0 + ldSeg;
        const bf16* b1 = gB1 + (size_t)(colBase + ldRow) * ldb + kbOff + k0 + ldSeg;
        uint32_t dA0 = smem_u32(&sAh[buf][ldRow][ldSeg]);
        uint32_t dA1 = smem_u32(&sAl[buf][ldRow][ldSeg]);
        uint32_t dB0 = smem_u32(&sBh[buf][ldRow][ldSeg]);
        uint32_t dB1 = smem_u32(&sBl[buf][ldRow][ldSeg]);
        cpa16(dA0, a0); cpa16(dA0 + 16, a0 + 8);
        cpa16(dA1, a1); cpa16(dA1 + 16, a1 + 8);
        cpa16(dB0, b0); cpa16(dB0 + 16, b0 + 8);
        cpa16(dB1, b1); cpa16(dB1 + 16, b1 + 8);
    };

    float acc[2][4][4] = {};
    const int NT = KDIM / 32;

    loadStage(0, 0);
    asm volatile("cp.async.commit_group;" ::: "memory");

    int aRow = lane & 15, aSel = (lane >> 4) * 8;   // ldmatrix x4 addressing
    int bRow = lane & 7,  bSel = ((lane >> 3) & 1) * 8;

    for (int t = 0; t < NT; t++) {
        int cur = t & 1;
        if (t + 1 < NT) {
            loadStage(t + 1, (t + 1) & 1);
            asm volatile("cp.async.commit_group;" ::: "memory");
            asm volatile("cp.async.wait_group 1;" ::: "memory");
        } else {
            asm volatile("cp.async.wait_group 0;" ::: "memory");
        }
        __syncthreads();

#pragma unroll
        for (int kk = 0; kk < 32; kk += 16) {
            uint32_t Afh[2][4], Afl[2][4], Bfh[4][2], Bfl[4][2];
#pragma unroll
            for (int mi = 0; mi < 2; mi++) {
                ldsm4(Afh[mi], smem_u32(&sAh[cur][wm + mi * 16 + aRow][kk + aSel]));
                ldsm4(Afl[mi], smem_u32(&sAl[cur][wm + mi * 16 + aRow][kk + aSel]));
            }
#pragma unroll
            for (int ni = 0; ni < 4; ni++) {
                ldsm2(Bfh[ni], smem_u32(&sBh[cur][wn + ni * 8 + bRow][kk + bSel]));
                ldsm2(Bfl[ni], smem_u32(&sBl[cur][wn + ni * 8 + bRow][kk + bSel]));
            }
#pragma unroll
            for (int mi = 0; mi < 2; mi++)
#pragma unroll
                for (int ni = 0; ni < 4; ni++) {
                    mma16816(acc[mi][ni], Afh[mi], Bfh[ni]);
                    mma16816(acc[mi][ni], Afh[mi], Bfl[ni]);
                    mma16816(acc[mi][ni], Afl[mi], Bfh[ni]);
                }
        }
        __syncthreads();
    }

    // ---- epilogue ----
    int t4 = lane >> 2, t2 = (lane & 3) * 2;
#pragma unroll
    for (int mi = 0; mi < 2; mi++) {
#pragma unroll
        for (int half = 0; half < 2; half++) {
            int lr = wm + mi * 16 + t4 + half * 8;       // local row in [0,64)
            int grow = rowBase + lr;
#pragma unroll
            for (int ni = 0; ni < 4; ni++) {
                float v0 = acc[mi][ni][half * 2 + 0];
                float v1 = acc[mi][ni][half * 2 + 1];
                int c0 = colBase + wn + ni * 8 + t2;
                if (EMODE == 0) {
                    float* po = Pf + (size_t)z * pStr + (size_t)grow * ldp;
                    po[c0] = v0; po[c0 + 1] = v1;
                } else if (EMODE == 1) {
                    int b = grow >> 7, ml = grow & 127;
                    bf16* ph = Ph + (size_t)b * (NH * MM);
                    bf16* pl = Pl + (size_t)b * (NH * MM);
                    float w0 = v0 + eb[c0], w1 = v1 + eb[c0 + 1];
                    bf16 h, l;
                    bsplit(w0, h, l); ph[(size_t)c0 * MM + ml] = h; pl[(size_t)c0 * MM + ml] = l;
                    bsplit(w1, h, l); ph[(size_t)(c0 + 1) * MM + ml] = h; pl[(size_t)(c0 + 1) * MM + ml] = l;
                } else {
                    float w0 = v0, w1 = v1;
                    if (EMODE == 3) {
                        float sa = sAv[grow];
                        w0 += sa * eb[c0]; w1 += sa * eb[c0 + 1];
                    }
                    w0 = fmaxf(w0, 0.f); w1 = fmaxf(w1, 0.f);
                    bf16* ph = Ph + (size_t)z * pStr + (size_t)grow * ldp;
                    bf16* pl = Pl + (size_t)z * pStr + (size_t)grow * ldp;
                    bf16 h, l;
                    bsplit(w0, h, l); ph[c0] = h; pl[c0] = l;
                    bsplit(w1, h, l); ph[c0 + 1] = h; pl[c0 + 1] = l;
                }
            }
        }
    }
}

// ---------------------------------------------------------------------------
// splits
// ---------------------------------------------------------------------------
__global__ void k_splitX(const float* __restrict__ X) {
    int idx = blockIdx.x * 256 + threadIdx.x;
    float f = X[idx];
    bf16 h, l;
    bsplit(f, h, l);          g_Xh[idx] = h;  g_Xl[idx] = l;
    float rf = fmaxf(f, 0.f);
    bsplit(rf, h, l);         g_Xrh[idx] = h; g_Xrl[idx] = l;
}

// transpose + split: out[n][k] = in[k][n]; in is [K][N] row-major (batched)
__global__ void k_splitWT(const float* __restrict__ W, bf16* __restrict__ Th,
                          bf16* __restrict__ Tl, int K, int N,
                          size_t inStr, size_t outStr) {
    __shared__ float t[32][33];
    int k0 = blockIdx.x * 32, n0 = blockIdx.y * 32;
    const float* in = W + blockIdx.z * inStr;
    int tx = threadIdx.x, ty = threadIdx.y;
    t[ty][tx] = in[(size_t)(k0 + ty) * N + n0 + tx];
    __syncthreads();
    float v = t[tx][ty];
    bf16 h, l; bsplit(v, h, l);
    size_t o = blockIdx.z * outStr + (size_t)(n0 + ty) * K + k0 + tx;
    Th[o] = h; Tl[o] = l;
}

// ---------------------------------------------------------------------------
// Persistent E reduction -> split bf16 aggE + sA
// ---------------------------------------------------------------------------
__global__ __launch_bounds__(256) void k_agge(const float* __restrict__ A,
                                              const float* __restrict__ E) {
    __shared__ float Ac[MM];
    __shared__ float red[8][EH];
    int t = threadIdx.x;
    int lane = t & 31, grp = t >> 5;

    for (int r = blockIdx.x; r < RR; r += gridDim.x) {
        int b = r >> 7, j = r & 127;
        if (t < MM) Ac[t] = A[(b * MM + t) * MM + j];
        __syncthreads();

        const float* Eb = E + ((size_t)b * MM * MM + j) * EH;
        float4 acc = {0.f, 0.f, 0.f, 0.f};
#pragma unroll
        for (int ii = 0; ii < MM; ii += 16) {
            int i0 = ii + grp, i1 = ii + 8 + grp;
            float4 v0 = *(const float4*)(Eb + (size_t)i0 * MM * EH + lane * 4);
            float4 v1 = *(const float4*)(Eb + (size_t)i1 * MM * EH + lane * 4);
            float a0 = Ac[i0], a1 = Ac[i1];
            acc.x += a0 * v0.x + a1 * v1.x;
            acc.y += a0 * v0.y + a1 * v1.y;
            acc.z += a0 * v0.z + a1 * v1.z;
            acc.w += a0 * v0.w + a1 * v1.w;
        }
        *(float4*)&red[grp][lane * 4] = acc;
        __syncthreads();
        if (t < EH) {
            float s = 0.f;
#pragma unroll
            for (int g = 0; g < 8; g++) s += red[g][t];
            bf16 h, l; bsplit(s, h, l);
            g_aEh[(size_t)r * EH + t] = h;
            g_aEl[(size_t)r * EH + t] = l;
        }
        if (t == 0) {
            float s = 0.f;
#pragma unroll
            for (int i = 0; i < MM; i++) s += Ac[i];
            g_sA[r] = s;
        }
        __syncthreads();
    }
}

// ---------------------------------------------------------------------------
__global__ __launch_bounds__(256) void k_final(const float* __restrict__ Wub,
                                               const float* __restrict__ w,
                                               float* __restrict__ out) {
    int r = blockIdx.x, n = threadIdx.x;
    size_t idx = (size_t)r * NH + n;
    float s = g_pO[0][idx] + g_pO[1][idx] + g_pO[2][idx];
    out[idx] = (s + Wub[n]) * w[r];
}

// ---------------------------------------------------------------------------
extern "C" void kernel_launch(void* const* d_in, const int* in_sizes, int n_in,
                              void* d_out, int out_size) {
    const float* X    = (const float*)d_in[0];
    const float* E    = (const float*)d_in[1];
    const float* A    = (const float*)d_in[2];
    const float* w    = (const float*)d_in[3];
    const float* Wv_w = (const float*)d_in[4];
    const float* Wv_b = (const float*)d_in[5];
    const float* We_w = (const float*)d_in[6];
    const float* We_b = (const float*)d_in[7];
    const float* Wu_w = (const float*)d_in[8];
    const float* Wu_b = (const float*)d_in[9];
    float* out = (float*)d_out;

    float *pO, *psA;
    cudaGetSymbolAddress((void**)&pO,  g_pO);
    cudaGetSymbolAddress((void**)&psA, g_sA);
    bf16 *Xh,*Xl,*Xrh,*Xrl,*WvTh,*WvTl,*WeTh,*WeTl,*WuTh,*WuTl,
         *ATh,*ATl,*NMTh,*NMTl,*hNh,*hNl,*aEh,*aEl,*hEh,*hEl;
    cudaGetSymbolAddress((void**)&Xh,  g_Xh);   cudaGetSymbolAddress((void**)&Xl,  g_Xl);
    cudaGetSymbolAddress((void**)&Xrh, g_Xrh);  cudaGetSymbolAddress((void**)&Xrl, g_Xrl);
    cudaGetSymbolAddress((void**)&WvTh,g_WvTh); cudaGetSymbolAddress((void**)&WvTl,g_WvTl);
    cudaGetSymbolAddress((void**)&WeTh,g_WeTh); cudaGetSymbolAddress((void**)&WeTl,g_WeTl);
    cudaGetSymbolAddress((void**)&WuTh,g_WuTh); cudaGetSymbolAddress((void**)&WuTl,g_WuTl);
    cudaGetSymbolAddress((void**)&ATh, g_ATh);  cudaGetSymbolAddress((void**)&ATl, g_ATl);
    cudaGetSymbolAddress((void**)&NMTh,g_NMTh); cudaGetSymbolAddress((void**)&NMTl,g_NMTl);
    cudaGetSymbolAddress((void**)&hNh, g_hNh);  cudaGetSymbolAddress((void**)&hNl, g_hNl);
    cudaGetSymbolAddress((void**)&aEh, g_aEh);  cudaGetSymbolAddress((void**)&aEl, g_aEl);
    cudaGetSymbolAddress((void**)&hEh, g_hEh);  cudaGetSymbolAddress((void**)&hEl, g_hEl);
    const size_t SL = (size_t)RR * NH;

    cudaStream_t sB, sC;
    cudaStreamCreateWithFlags(&sB, cudaStreamNonBlocking);
    cudaStreamCreateWithFlags(&sC, cudaStreamNonBlocking);
    cudaEvent_t e0, eX, eWu, eAT, eWe, eB, eC;
    cudaEventCreateWithFlags(&e0,  cudaEventDisableTiming);
    cudaEventCreateWithFlags(&eX,  cudaEventDisableTiming);
    cudaEventCreateWithFlags(&eWu, cudaEventDisableTiming);
    cudaEventCreateWithFlags(&eAT, cudaEventDisableTiming);
    cudaEventCreateWithFlags(&eWe, cudaEventDisableTiming);
    cudaEventCreateWithFlags(&eB,  cudaEventDisableTiming);
    cudaEventCreateWithFlags(&eC,  cudaEventDisableTiming);

    dim3 t32(32, 32);

    cudaEventRecord(e0, 0);
    cudaStreamWaitEvent(sB, e0, 0);
    cudaStreamWaitEvent(sC, e0, 0);

    // ---- sB: E reduction (DRAM-bound, starts immediately) ----
    k_agge<<<512, 256, 0, sB>>>(A, E);

    // ---- sC: operand prep ----
    k_splitWT<<<dim3(4, 4, 16), t32, 0, sC>>>(A, ATh, ATl, MM, MM,
                                              (size_t)MM * MM, (size_t)MM * MM);
    cudaEventRecord(eAT, sC);
    k_splitWT<<<dim3(4, 4, 1),  t32, 0, sC>>>(We_w, WeTh, WeTl, EH, EH, 0, 0);
    cudaEventRecord(eWe, sC);

    // ---- s0: splits + node chain ----
    k_splitX<<<RR, 256>>>(X);
    cudaEventRecord(eX, 0);
    k_splitWT<<<dim3(8, 8, 1),  t32>>>(Wv_w, WvTh, WvTl, NH, NH, 0, 0);
    k_splitWT<<<dim3(20, 8, 1), t32>>>(Wu_w, WuTh, WuTl, 640, NH, 0, 0);
    cudaEventRecord(eWu, 0);

    // nodeMap^T = (X @ Wv + Wv_b)^T   (EMODE1)
    tmm<256, 1><<<dim3(32, 4, 1), 128>>>(
        Xh, Xl, NH, 0, WvTh, WvTl, NH, 0, 0,
        nullptr, Wv_b, nullptr, NMTh, NMTl, 0, 0);
    // hN = relu(A^T @ nodeMap) per batch (EMODE2)
    cudaStreamWaitEvent(0, eAT, 0);
    tmm<128, 2><<<dim3(2, 4, 16), 128>>>(
        ATh, ATl, MM, (size_t)MM * MM, NMTh, NMTl, MM, 0, (size_t)NH * MM,
        nullptr, nullptr, nullptr, hNh, hNl, NH, (size_t)MM * NH);
    // pO[0] = hN @ Wu[0:256]
    tmm<256, 0><<<dim3(32, 4, 1), 128>>>(
        hNh, hNl, NH, 0, WuTh, WuTl, 640, 0, 0,
        nullptr, nullptr, pO, nullptr, nullptr, NH, 0);

    // ---- sC: x branch: pO[1] = relu(X) @ Wu[384:640] ----
    cudaStreamWaitEvent(sC, eX, 0);
    cudaStreamWaitEvent(sC, eWu, 0);
    tmm<256, 0><<<dim3(32, 4, 1), 128, 0, sC>>>(
        Xrh, Xrl, NH, 0, WuTh, WuTl, 640, 384, 0,
        nullptr, nullptr, pO + 1 * SL, nullptr, nullptr, NH, 0);
    cudaEventRecord(eC, sC);

    // ---- sB: edge chain ----
    cudaStreamWaitEvent(sB, eWe, 0);
    // hE = relu(aggE @ We + sA*We_b)  (EMODE3)
    tmm<128, 3><<<dim3(32, 2, 1), 128, 0, sB>>>(
        aEh, aEl, EH, 0, WeTh, WeTl, EH, 0, 0,
        psA, We_b, nullptr, hEh, hEl, EH, 0);
    // pO[2] = hE @ Wu[256:384]
    cudaStreamWaitEvent(sB, eWu, 0);
    tmm<128, 0><<<dim3(32, 4, 1), 128, 0, sB>>>(
        hEh, hEl, EH, 0, WuTh, WuTl, 640, 256, 0,
        nullptr, nullptr, pO + 2 * SL, nullptr, nullptr, NH, 0);
    cudaEventRecord(eB, sB);

    // ---- join ----
    cudaStreamWaitEvent(0, eB, 0);
    cudaStreamWaitEvent(0, eC, 0);
    k_final<<<RR, 256>>>(Wu_b, w, out);

    cudaEventDestroy(e0);  cudaEventDestroy(eX);  cudaEventDestroy(eWu);
    cudaEventDestroy(eAT); cudaEventDestroy(eWe); cudaEventDestroy(eB);
    cudaEventDestroy(eC);
    cudaStreamDestroy(sB); cudaStreamDestroy(sC);
}